// round 10
// baseline (speedup 1.0000x reference)
#include <cuda_runtime.h>
#include <cstdint>

#define N_NODES 8192
#define KNN     32
#define NE      (N_NODES * KNN)
#define FULL    0xffffffffu

#define G       16
#define NBINS   (G * G)
#define X0      0.1f
#define SINV    (G / 0.9f)     // bins per coordinate unit
#define SW      (0.9f / G)     // bin width

#define NBLK    1024
#define TPB     256
#define WPB     (TPB / 32)             // 8 warps/block
#define PPB     (N_NODES / NBLK)       // 8 points per block (prep)

#define PADKEY  0xffffffffffffffffULL
#define PADHI   0xffffffffu

// Scratch (__device__ globals; zero-initialized at load; barrier/hist state
// reset at end of every run for graph replay)
__device__ float4 g_attr[N_NODES];     // {w, h, cx, cy} original order
__device__ float4 g_sorted[N_NODES];   // bin order: {cx, cy, sq, bits(idx)}
__device__ int    g_binStart[NBINS + 1];
__device__ int    g_hist[NBINS];
__device__ int    g_bar1, g_flagB, g_bar2, g_obs2;

__device__ __forceinline__ int bin_of(float c) {
    int b = (int)((c - X0) * SINV);
    return min(max(b, 0), G - 1);
}

// monotonic float<->uint order mapping
__device__ __forceinline__ unsigned fkey(float f) {
    unsigned u = __float_as_uint(f);
    return (u & 0x80000000u) ? ~u : (u | 0x80000000u);
}
__device__ __forceinline__ float unfkey(unsigned k) {
    unsigned u = (k & 0x80000000u) ? (k ^ 0x80000000u) : ~k;
    return __uint_as_float(u);
}

__device__ __forceinline__ unsigned long long umin64(unsigned long long a,
                                                     unsigned long long b) {
    return a < b ? a : b;
}
__device__ __forceinline__ unsigned long long umax64(unsigned long long a,
                                                     unsigned long long b) {
    return a > b ? a : b;
}

__global__ void __launch_bounds__(TPB, 7)     // 7 blocks/SM => all 1024 resident
fused_kernel(const float* __restrict__ loc, float* __restrict__ out) {
    const int t = threadIdx.x;
    const int b = blockIdx.x;
    const int lane = t & 31;
    const float INF = __int_as_float(0x7f800000);

    // ================= Phase A: pack + global histogram (rank = old) =====
    float cxr = 0.f, cyr = 0.f, sqr = 0.f;
    int   binr = 0, ir = 0, rank = 0;
    if (t < PPB) {
        ir = b * PPB + t;
        // row byte offset 40*i+16 is 8-aligned -> float2 loads [w,h],[cx,cy]
        const float2* p2 = reinterpret_cast<const float2*>(loc + ir * 10 + 4);
        float2 wh = p2[0];
        float2 cc = p2[1];
        // sq matches jnp.sum(pos*pos): rn(cx*cx)+rn(cy*cy), no fma
        float sq = __fadd_rn(__fmul_rn(cc.x, cc.x), __fmul_rn(cc.y, cc.y));
        g_attr[ir] = make_float4(wh.x, wh.y, cc.x, cc.y);
        binr = bin_of(cc.y) * G + bin_of(cc.x);
        rank = atomicAdd(&g_hist[binr], 1);  // in-bin rank
        cxr = cc.x; cyr = cc.y; sqr = sq;
    }
    __threadfence();
    __syncthreads();
    if (t == 0) atomicAdd(&g_bar1, 1);

    // ================= Phase B: block 0 scans the 256 bins ===============
    if (b == 0) {
        if (t == 0) {
            while (((volatile int*)&g_bar1)[0] < NBLK) __nanosleep(32);
        }
        __syncthreads();
        __threadfence();
        __shared__ int wsum[8];
        int v = 0, h = 0;
        if (t < NBINS) {
            h = g_hist[t];
            v = h;
            #pragma unroll
            for (int off = 1; off < 32; off <<= 1) {
                int n = __shfl_up_sync(FULL, v, off);
                if (lane >= off) v += n;
            }
            if (lane == 31) wsum[t >> 5] = v;
        }
        __syncthreads();
        if (t < 8) {
            int s = wsum[t];
            #pragma unroll
            for (int off = 1; off < 8; off <<= 1) {
                int n = __shfl_up_sync(0xffu, s, off);
                if (t >= off) s += n;
            }
            wsum[t] = s;
        }
        __syncthreads();
        if (t < NBINS) {
            int incl = v + ((t >= 32) ? wsum[(t >> 5) - 1] : 0);
            g_binStart[t] = incl - h;
            if (t == NBINS - 1) g_binStart[NBINS] = incl;
        }
        __threadfence();
        __syncthreads();
        if (t == 0) atomicExch(&g_flagB, 1);
    }
    if (t == 0) {
        while (((volatile int*)&g_flagB)[0] == 0) __nanosleep(32);
    }
    __syncthreads();
    __threadfence();

    // ================= Phase C: scatter at binStart + rank ===============
    if (t < PPB) {
        g_sorted[g_binStart[binr] + rank] =
            make_float4(cxr, cyr, sqr, __uint_as_float((unsigned)ir));
    }
    __threadfence();
    __syncthreads();
    // grid barrier 2 + deadlock-free reset by the LAST observer
    if (t == 0) {
        atomicAdd(&g_bar2, 1);
        while (((volatile int*)&g_bar2)[0] < NBLK) __nanosleep(32);
        int o = atomicAdd(&g_obs2, 1);
        if (o == NBLK - 1) {  // all blocks passed both polls: safe to reset
            #pragma unroll 4
            for (int i = 0; i < NBINS; i++) g_hist[i] = 0;
            g_bar1 = 0; g_flagB = 0; g_bar2 = 0; g_obs2 = 0;
            __threadfence();
        }
    }
    __syncthreads();
    __threadfence();

    // ================= Phase D: KNN (1 query per warp) ====================
    const int p = b * WPB + (t >> 5);   // sorted position (bin-ordered)

    const float4 sp = g_sorted[p];
    const unsigned q = __float_as_uint(sp.w);
    const float  qx  = sp.x, qy = sp.y, sqi = sp.z;
    const float  m2x = -2.0f * qx, m2y = -2.0f * qy;  // exact (×2)
    const int bx = bin_of(qx);
    const int by = bin_of(qy);

    // exact reference-rounded key: (fkey(d2) << 32) | idx
    auto exact_key = [&](float px, float py, float pz, unsigned j) -> unsigned long long {
        float dot = __fmaf_rn(py, qy, __fmul_rn(px, qx));
        float d2  = __fsub_rn(__fadd_rn(sqi, pz), __fmul_rn(2.0f, dot));
        if (j == q) d2 = INF;  // no self loops
        return ((unsigned long long)fkey(d2) << 32) | j;
    };

    unsigned long long slot = PADKEY;  // slots start +inf, stay sorted asc
    float curMax = INF;
    float thresh = INF;

    auto update_thresh = [&]() {
        unsigned hi = (unsigned)(__shfl_sync(FULL, slot, 31) >> 32);
        // PAD sentinel decodes to NaN -> clamp to +INF
        curMax = (hi == PADHI) ? INF : unfkey(hi);
        thresh = (hi == PADHI) ? INF : (curMax - sqi + 2e-5f);
    };

    auto scan_range = [&](int lo, int hiend) {
        if (lo >= hiend) return;
        int base = lo;
        int i = base + lane;
        bool valid = (i < hiend);
        float4 pp;
        if (valid) pp = g_sorted[i];
        while (base < hiend) {
            // prefetch next chunk before the ballot/merge dependency chain
            int nbase = base + 32;
            float4 np;
            bool nvalid = false;
            if (nbase < hiend) {
                int ni = nbase + lane;
                nvalid = (ni < hiend);
                if (nvalid) np = g_sorted[ni];
            }
            float score = valid
                ? __fmaf_rn(pp.y, m2y, __fmaf_rn(pp.x, m2x, pp.z)) : INF;
            bool hit = (score < thresh);
            unsigned mask = __ballot_sync(FULL, hit);
            if (mask) {
                unsigned long long ck = hit
                    ? exact_key(pp.x, pp.y, pp.z, __float_as_uint(pp.w))
                    : PADKEY;
                if (__popc(mask) <= 3) {
                    // few hits: serial shift-insert (self-rejecting)
                    do {
                        int srcl = __ffs(mask) - 1;
                        mask &= mask - 1;
                        unsigned long long kk = __shfl_sync(FULL, ck, srcl);
                        bool gt = (slot > kk);
                        unsigned mm = __ballot_sync(FULL, gt);
                        unsigned long long o = __shfl_up_sync(FULL, slot, 1);
                        if (gt) slot = (lane == __ffs(mm) - 1) ? kk : o;
                    } while (mask);
                } else {
                    // many hits: bitonic sort candidates asc (15 stages)
                    #pragma unroll
                    for (int k2 = 2; k2 <= 32; k2 <<= 1) {
                        #pragma unroll
                        for (int j = k2 >> 1; j > 0; j >>= 1) {
                            unsigned long long o = __shfl_xor_sync(FULL, ck, j);
                            bool keepmin = (((lane & k2) == 0) == ((lane & j) == 0));
                            ck = keepmin ? umin64(ck, o) : umax64(ck, o);
                        }
                    }
                    // top-32 merge: min(A, reverse(B)) bitonic; 5-stage clean
                    unsigned long long br = __shfl_sync(FULL, ck, 31 - lane);
                    unsigned long long m  = umin64(slot, br);
                    #pragma unroll
                    for (int j = 16; j > 0; j >>= 1) {
                        unsigned long long o = __shfl_xor_sync(FULL, m, j);
                        m = ((lane & j) == 0) ? umin64(m, o) : umax64(m, o);
                    }
                    slot = m;
                }
                update_thresh();
            }
            pp = np; valid = nvalid; base = nbase;
        }
    };

    // ---- anisotropic rectangle growth from the home bin ----
    int xlo = bx, xhi = bx, ylo = by, yhi = by;
    scan_range(g_binStart[by * G + bx], g_binStart[by * G + bx + 1]);
    while (true) {
        bool grew = false;
        if (xlo > 0) {
            float d = qx - (X0 + xlo * SW);
            if (__fmul_rn(d, d) <= curMax + 2e-5f) {
                int c = xlo - 1;
                for (int y = ylo; y <= yhi; y++)
                    scan_range(g_binStart[y * G + c], g_binStart[y * G + c + 1]);
                xlo = c; grew = true;
            }
        }
        if (xhi < G - 1) {
            float d = (X0 + (xhi + 1) * SW) - qx;
            if (__fmul_rn(d, d) <= curMax + 2e-5f) {
                int c = xhi + 1;
                for (int y = ylo; y <= yhi; y++)
                    scan_range(g_binStart[y * G + c], g_binStart[y * G + c + 1]);
                xhi = c; grew = true;
            }
        }
        if (ylo > 0) {
            float d = qy - (X0 + ylo * SW);
            if (__fmul_rn(d, d) <= curMax + 2e-5f) {
                int r = (ylo - 1) * G;
                scan_range(g_binStart[r + xlo], g_binStart[r + xhi + 1]);
                ylo--; grew = true;
            }
        }
        if (yhi < G - 1) {
            float d = (X0 + (yhi + 1) * SW) - qy;
            if (__fmul_rn(d, d) <= curMax + 2e-5f) {
                int r = (yhi + 1) * G;
                scan_range(g_binStart[r + xlo], g_binStart[r + xhi + 1]);
                yhi++; grew = true;
            }
        }
        if (!grew) break;
    }

    // ---- outputs (slots ascending = exact top_k order) ----
    const int e = (int)q * KNN + lane;
    const int s = (int)(unsigned)(slot & 0xffffffffu);

    out[e]      = (float)s;        // edge_index[0] (sources)
    out[NE + e] = (float)q;        // edge_index[1] (targets)

    float4 as = g_attr[s];
    float4 at = g_attr[q];
    float hsum = __fadd_rn(as.y, at.y);
    float f1 = __fdiv_rn(__fmul_rn(2.0f, __fsub_rn(as.z, at.z)), hsum);
    float f2 = __fdiv_rn(__fmul_rn(2.0f, __fsub_rn(as.w, at.w)), hsum);
    float f3 = logf(__fdiv_rn(as.x, at.x));
    float f4 = logf(__fdiv_rn(as.y, at.y));

    float4* ao = reinterpret_cast<float4*>(out + 2 * NE) + e;
    *ao = make_float4(f1, f2, f3, f4);
}

extern "C" void kernel_launch(void* const* d_in, const int* in_sizes, int n_in,
                              void* d_out, int out_size) {
    const float* loc = (const float*)d_in[1];
    float* out = (float*)d_out;

    fused_kernel<<<NBLK, TPB>>>(loc, out);
}

// round 11
// speedup vs baseline: 1.1099x; 1.1099x over previous
#include <cuda_runtime.h>
#include <cstdint>

#define N_NODES 8192
#define KNN     32
#define NE      (N_NODES * KNN)
#define FULL    0xffffffffu

#define G       16
#define NBINS   (G * G)
#define X0      0.1f
#define SINV    (G / 0.9f)     // bins per coordinate unit
#define SW      (0.9f / G)     // bin width

#define NBLK    1024
#define TPB     256
#define WPB     (TPB / 32)             // 8 warps/block
#define PPB     (N_NODES / NBLK)       // 8 points per block (prep)

#define PADKEY  0xffffffffffffffffULL
#define PADHI   0xffffffffu

// Scratch (__device__ globals; zero-initialized at load; barrier/hist state
// reset at end of every run for graph replay)
__device__ float4 g_attr[N_NODES];     // {w, h, cx, cy} original order
__device__ float4 g_sorted[N_NODES];   // bin order: {cx, cy, sq, bits(idx)}
__device__ int    g_binStart[NBINS + 1];
__device__ int    g_hist[NBINS];
__device__ int    g_bar1, g_flagB, g_bar2, g_obs2;

__device__ __forceinline__ int bin_of(float c) {
    int b = (int)((c - X0) * SINV);
    return min(max(b, 0), G - 1);
}

// monotonic float<->uint order mapping
__device__ __forceinline__ unsigned fkey(float f) {
    unsigned u = __float_as_uint(f);
    return (u & 0x80000000u) ? ~u : (u | 0x80000000u);
}
__device__ __forceinline__ float unfkey(unsigned k) {
    unsigned u = (k & 0x80000000u) ? (k ^ 0x80000000u) : ~k;
    return __uint_as_float(u);
}

__device__ __forceinline__ unsigned long long umin64(unsigned long long a,
                                                     unsigned long long b) {
    return a < b ? a : b;
}
__device__ __forceinline__ unsigned long long umax64(unsigned long long a,
                                                     unsigned long long b) {
    return a > b ? a : b;
}

__global__ void __launch_bounds__(TPB, 7)     // 7 blocks/SM => all 1024 resident
fused_kernel(const float* __restrict__ loc, float* __restrict__ out) {
    const int t = threadIdx.x;
    const int b = blockIdx.x;
    const int lane = t & 31;
    const float INF = __int_as_float(0x7f800000);

    // ================= Phase A: pack + global histogram (rank = old) =====
    float cxr = 0.f, cyr = 0.f, sqr = 0.f;
    int   binr = 0, ir = 0, rank = 0;
    if (t < PPB) {
        ir = b * PPB + t;
        // row byte offset 40*i+16 is 8-aligned -> float2 loads [w,h],[cx,cy]
        const float2* p2 = reinterpret_cast<const float2*>(loc + ir * 10 + 4);
        float2 wh = p2[0];
        float2 cc = p2[1];
        // sq matches jnp.sum(pos*pos): rn(cx*cx)+rn(cy*cy), no fma
        float sq = __fadd_rn(__fmul_rn(cc.x, cc.x), __fmul_rn(cc.y, cc.y));
        g_attr[ir] = make_float4(wh.x, wh.y, cc.x, cc.y);
        binr = bin_of(cc.y) * G + bin_of(cc.x);
        rank = atomicAdd(&g_hist[binr], 1);  // in-bin rank
        cxr = cc.x; cyr = cc.y; sqr = sq;
    }
    __threadfence();
    __syncthreads();
    if (t == 0) atomicAdd(&g_bar1, 1);

    // ================= Phase B: block 0 scans the 256 bins ===============
    if (b == 0) {
        if (t == 0) {
            while (((volatile int*)&g_bar1)[0] < NBLK) __nanosleep(32);
        }
        __syncthreads();
        __threadfence();
        __shared__ int wsum[8];
        int v = 0, h = 0;
        if (t < NBINS) {
            h = g_hist[t];
            v = h;
            #pragma unroll
            for (int off = 1; off < 32; off <<= 1) {
                int n = __shfl_up_sync(FULL, v, off);
                if (lane >= off) v += n;
            }
            if (lane == 31) wsum[t >> 5] = v;
        }
        __syncthreads();
        if (t < 8) {
            int s = wsum[t];
            #pragma unroll
            for (int off = 1; off < 8; off <<= 1) {
                int n = __shfl_up_sync(0xffu, s, off);
                if (t >= off) s += n;
            }
            wsum[t] = s;
        }
        __syncthreads();
        if (t < NBINS) {
            int incl = v + ((t >= 32) ? wsum[(t >> 5) - 1] : 0);
            g_binStart[t] = incl - h;
            if (t == NBINS - 1) g_binStart[NBINS] = incl;
        }
        __threadfence();
        __syncthreads();
        if (t == 0) atomicExch(&g_flagB, 1);
    }
    if (t == 0) {
        while (((volatile int*)&g_flagB)[0] == 0) __nanosleep(32);
    }
    __syncthreads();
    __threadfence();

    // ================= Phase C: scatter at binStart + rank ===============
    if (t < PPB) {
        g_sorted[g_binStart[binr] + rank] =
            make_float4(cxr, cyr, sqr, __uint_as_float((unsigned)ir));
    }
    __threadfence();
    __syncthreads();
    // grid barrier 2 + deadlock-free reset by the LAST observer
    if (t == 0) {
        atomicAdd(&g_bar2, 1);
        while (((volatile int*)&g_bar2)[0] < NBLK) __nanosleep(32);
        int o = atomicAdd(&g_obs2, 1);
        if (o == NBLK - 1) {  // all blocks passed both polls: safe to reset
            #pragma unroll 4
            for (int i = 0; i < NBINS; i++) g_hist[i] = 0;
            g_bar1 = 0; g_flagB = 0; g_bar2 = 0; g_obs2 = 0;
            __threadfence();
        }
    }
    __syncthreads();
    __threadfence();

    // ================= Phase D: KNN (1 query per warp) ====================
    const int p = b * WPB + (t >> 5);   // sorted position (bin-ordered)

    const float4 sp = g_sorted[p];
    const unsigned q = __float_as_uint(sp.w);
    const float  qx  = sp.x, qy = sp.y, sqi = sp.z;
    const float  m2x = -2.0f * qx, m2y = -2.0f * qy;  // exact (×2)
    const int bx = bin_of(qx);
    const int by = bin_of(qy);

    // exact reference-rounded key: (fkey(d2) << 32) | idx
    auto exact_key = [&](float px, float py, float pz, unsigned j) -> unsigned long long {
        float dot = __fmaf_rn(py, qy, __fmul_rn(px, qx));
        float d2  = __fsub_rn(__fadd_rn(sqi, pz), __fmul_rn(2.0f, dot));
        if (j == q) d2 = INF;  // no self loops
        return ((unsigned long long)fkey(d2) << 32) | j;
    };

    unsigned long long slot = PADKEY;  // slots start +inf, stay sorted asc
    float curMax = INF;
    float thresh = INF;

    auto update_thresh = [&]() {
        unsigned hi = (unsigned)(__shfl_sync(FULL, slot, 31) >> 32);
        // PAD sentinel decodes to NaN -> clamp to +INF
        curMax = (hi == PADHI) ? INF : unfkey(hi);
        thresh = (hi == PADHI) ? INF : (curMax - sqi + 2e-5f);
    };

    auto scan_range = [&](int lo, int hiend) {
        for (int base = lo; base < hiend; base += 32) {
            int i = base + lane;
            float4 pp = make_float4(0.0f, 0.0f, INF, 0.0f);
            float score = INF;
            unsigned jidx = 0;
            if (i < hiend) {
                pp = g_sorted[i];
                jidx = __float_as_uint(pp.w);
                score = __fmaf_rn(pp.y, m2y, __fmaf_rn(pp.x, m2x, pp.z));
            }
            bool hit = (score < thresh) && (i < hiend);
            unsigned mask = __ballot_sync(FULL, hit);
            if (!mask) continue;
            unsigned long long ck = hit ? exact_key(pp.x, pp.y, pp.z, jidx)
                                        : PADKEY;
            if (__popc(mask) <= 5) {
                // few hits: serial shift-insert (self-rejecting)
                do {
                    int srcl = __ffs(mask) - 1;
                    mask &= mask - 1;
                    unsigned long long kk = __shfl_sync(FULL, ck, srcl);
                    bool gt = (slot > kk);
                    unsigned mm = __ballot_sync(FULL, gt);
                    unsigned long long o = __shfl_up_sync(FULL, slot, 1);
                    if (gt) slot = (lane == __ffs(mm) - 1) ? kk : o;
                } while (mask);
            } else {
                // many hits: bitonic sort candidates asc (15 stages)
                #pragma unroll
                for (int k2 = 2; k2 <= 32; k2 <<= 1) {
                    #pragma unroll
                    for (int j = k2 >> 1; j > 0; j >>= 1) {
                        unsigned long long o = __shfl_xor_sync(FULL, ck, j);
                        bool keepmin = (((lane & k2) == 0) == ((lane & j) == 0));
                        ck = keepmin ? umin64(ck, o) : umax64(ck, o);
                    }
                }
                // top-32 merge: min(A, reverse(B)) bitonic; 5-stage clean
                unsigned long long br = __shfl_sync(FULL, ck, 31 - lane);
                unsigned long long m  = umin64(slot, br);
                #pragma unroll
                for (int j = 16; j > 0; j >>= 1) {
                    unsigned long long o = __shfl_xor_sync(FULL, m, j);
                    m = ((lane & j) == 0) ? umin64(m, o) : umax64(m, o);
                }
                slot = m;
            }
            update_thresh();
        }
    };

    // home bin FIRST (tightest early threshold), then rest of 3-bin row
    const int bxlo1 = max(bx - 1, 0), bxhi1 = min(bx + 1, G - 1);
    const int rowb = by * G;
    const int hsb = g_binStart[rowb + bx], heb = g_binStart[rowb + bx + 1];
    scan_range(hsb, heb);
    scan_range(g_binStart[rowb + bxlo1], hsb);
    scan_range(heb, g_binStart[rowb + bxhi1 + 1]);
    if (by - 1 >= 0) {
        int r = (by - 1) * G;
        scan_range(g_binStart[r + bxlo1], g_binStart[r + bxhi1 + 1]);
    }
    if (by + 1 <= G - 1) {
        int r = (by + 1) * G;
        scan_range(g_binStart[r + bxlo1], g_binStart[r + bxhi1 + 1]);
    }

    // Chebyshev rings m>=2 with exact stop bound (curMax=INF never stops)
    for (int m = 2; m <= 2 * G; m++) {
        {
            int mm1 = m - 1;
            float dl = (bx - mm1 > 0)     ? (qx - (X0 + (bx - mm1) * SW))     : INF;
            float dr = (bx + mm1 < G - 1) ? ((X0 + (bx + mm1 + 1) * SW) - qx) : INF;
            float db = (by - mm1 > 0)     ? (qy - (X0 + (by - mm1) * SW))     : INF;
            float dt = (by + mm1 < G - 1) ? ((X0 + (by + mm1 + 1) * SW) - qy) : INF;
            float dmin = fminf(fminf(dl, dr), fminf(db, dt));
            if (dmin * dmin > curMax + 2e-5f) break;
        }
        int bxlo = max(bx - m, 0), bxhi = min(bx + m, G - 1);
        if (by - m >= 0) {
            int r = (by - m) * G;
            scan_range(g_binStart[r + bxlo], g_binStart[r + bxhi + 1]);
        }
        if (by + m <= G - 1) {
            int r = (by + m) * G;
            scan_range(g_binStart[r + bxlo], g_binStart[r + bxhi + 1]);
        }
        int ylo = max(by - m + 1, 0), yhi = min(by + m - 1, G - 1);
        if (bx - m >= 0) {
            for (int y = ylo; y <= yhi; y++) {
                int bb = y * G + bx - m;
                scan_range(g_binStart[bb], g_binStart[bb + 1]);
            }
        }
        if (bx + m <= G - 1) {
            for (int y = ylo; y <= yhi; y++) {
                int bb = y * G + bx + m;
                scan_range(g_binStart[bb], g_binStart[bb + 1]);
            }
        }
    }

    // ---- outputs (slots ascending = exact top_k order) ----
    const int e = (int)q * KNN + lane;
    const int s = (int)(unsigned)(slot & 0xffffffffu);

    out[e]      = (float)s;        // edge_index[0] (sources)
    out[NE + e] = (float)q;        // edge_index[1] (targets)

    float4 as = g_attr[s];
    float4 at = g_attr[q];
    float hsum = __fadd_rn(as.y, at.y);
    float f1 = __fdiv_rn(__fmul_rn(2.0f, __fsub_rn(as.z, at.z)), hsum);
    float f2 = __fdiv_rn(__fmul_rn(2.0f, __fsub_rn(as.w, at.w)), hsum);
    float f3 = logf(__fdiv_rn(as.x, at.x));
    float f4 = logf(__fdiv_rn(as.y, at.y));

    float4* ao = reinterpret_cast<float4*>(out + 2 * NE) + e;
    *ao = make_float4(f1, f2, f3, f4);
}

extern "C" void kernel_launch(void* const* d_in, const int* in_sizes, int n_in,
                              void* d_out, int out_size) {
    const float* loc = (const float*)d_in[1];
    float* out = (float*)d_out;

    fused_kernel<<<NBLK, TPB>>>(loc, out);
}

// round 12
// speedup vs baseline: 1.1355x; 1.0230x over previous
#include <cuda_runtime.h>
#include <cstdint>

#define N_NODES 8192
#define KNN     32
#define NE      (N_NODES * KNN)
#define FULL    0xffffffffu

#define G       16
#define NBINS   (G * G)
#define X0      0.1f
#define SINV    (G / 0.9f)     // bins per coordinate unit
#define SW      (0.9f / G)     // bin width

#define NBLK    1024
#define TPB     256
#define WPB     (TPB / 32)             // 8 warps/block
#define PPB     (N_NODES / NBLK)       // 8 points per block (prep)

#define PADKEY  0xffffffffffffffffULL
#define PADHI   0xffffffffu

// Scratch (__device__ globals; zero-initialized at load; barrier/hist state
// reset at end of every run for graph replay)
__device__ float4 g_attr[N_NODES];     // {w, h, cx, cy} original order
__device__ float4 g_sorted[N_NODES];   // bin order: {cx, cy, sq, bits(idx)}
__device__ int    g_binStart[NBINS + 1];
__device__ int    g_hist[NBINS];
__device__ int    g_bar1, g_flagB, g_bar2, g_obs2;

__device__ __forceinline__ int bin_of(float c) {
    int b = (int)((c - X0) * SINV);
    return min(max(b, 0), G - 1);
}

// monotonic float<->uint order mapping
__device__ __forceinline__ unsigned fkey(float f) {
    unsigned u = __float_as_uint(f);
    return (u & 0x80000000u) ? ~u : (u | 0x80000000u);
}
__device__ __forceinline__ float unfkey(unsigned k) {
    unsigned u = (k & 0x80000000u) ? (k ^ 0x80000000u) : ~k;
    return __uint_as_float(u);
}

__device__ __forceinline__ unsigned long long umin64(unsigned long long a,
                                                     unsigned long long b) {
    return a < b ? a : b;
}
__device__ __forceinline__ unsigned long long umax64(unsigned long long a,
                                                     unsigned long long b) {
    return a > b ? a : b;
}

__global__ void __launch_bounds__(TPB, 8)   // 8 blocks/SM, 64 warps/SM, regs<=32
fused_kernel(const float* __restrict__ loc, float* __restrict__ out) {
    const int t = threadIdx.x;
    const int b = blockIdx.x;
    const int lane = t & 31;
    const float INF = __int_as_float(0x7f800000);

    // ================= Phase A: pack + global histogram (rank = old) =====
    float cxr = 0.f, cyr = 0.f, sqr = 0.f;
    int   binr = 0, ir = 0, rank = 0;
    if (t < PPB) {
        ir = b * PPB + t;
        // row byte offset 40*i+16 is 8-aligned -> float2 loads [w,h],[cx,cy]
        const float2* p2 = reinterpret_cast<const float2*>(loc + ir * 10 + 4);
        float2 wh = p2[0];
        float2 cc = p2[1];
        // sq matches jnp.sum(pos*pos): rn(cx*cx)+rn(cy*cy), no fma
        float sq = __fadd_rn(__fmul_rn(cc.x, cc.x), __fmul_rn(cc.y, cc.y));
        g_attr[ir] = make_float4(wh.x, wh.y, cc.x, cc.y);
        binr = bin_of(cc.y) * G + bin_of(cc.x);
        rank = atomicAdd(&g_hist[binr], 1);  // in-bin rank
        cxr = cc.x; cyr = cc.y; sqr = sq;
    }
    __threadfence();
    __syncthreads();
    if (t == 0) atomicAdd(&g_bar1, 1);

    // ================= Phase B: block 0 scans the 256 bins ===============
    if (b == 0) {
        if (t == 0) {
            while (((volatile int*)&g_bar1)[0] < NBLK) __nanosleep(32);
        }
        __syncthreads();
        __threadfence();
        __shared__ int wsum[8];
        int v = 0, h = 0;
        if (t < NBINS) {
            h = g_hist[t];
            v = h;
            #pragma unroll
            for (int off = 1; off < 32; off <<= 1) {
                int n = __shfl_up_sync(FULL, v, off);
                if (lane >= off) v += n;
            }
            if (lane == 31) wsum[t >> 5] = v;
        }
        __syncthreads();
        if (t < 8) {
            int s = wsum[t];
            #pragma unroll
            for (int off = 1; off < 8; off <<= 1) {
                int n = __shfl_up_sync(0xffu, s, off);
                if (t >= off) s += n;
            }
            wsum[t] = s;
        }
        __syncthreads();
        if (t < NBINS) {
            int incl = v + ((t >= 32) ? wsum[(t >> 5) - 1] : 0);
            g_binStart[t] = incl - h;
            if (t == NBINS - 1) g_binStart[NBINS] = incl;
        }
        __threadfence();
        __syncthreads();
        if (t == 0) atomicExch(&g_flagB, 1);
    }
    if (t == 0) {
        while (((volatile int*)&g_flagB)[0] == 0) __nanosleep(32);
    }
    __syncthreads();
    __threadfence();

    // ================= Phase C: scatter at binStart + rank ===============
    if (t < PPB) {
        g_sorted[g_binStart[binr] + rank] =
            make_float4(cxr, cyr, sqr, __uint_as_float((unsigned)ir));
    }
    __threadfence();
    __syncthreads();
    // grid barrier 2 + deadlock-free reset by the LAST observer
    if (t == 0) {
        atomicAdd(&g_bar2, 1);
        while (((volatile int*)&g_bar2)[0] < NBLK) __nanosleep(32);
        int o = atomicAdd(&g_obs2, 1);
        if (o == NBLK - 1) {  // all blocks passed both polls: safe to reset
            #pragma unroll 4
            for (int i = 0; i < NBINS; i++) g_hist[i] = 0;
            g_bar1 = 0; g_flagB = 0; g_bar2 = 0; g_obs2 = 0;
            __threadfence();
        }
    }
    __syncthreads();
    __threadfence();

    // ================= Phase D: KNN (1 query per warp) ====================
    const int p = b * WPB + (t >> 5);   // sorted position (bin-ordered)

    const float4 sp = g_sorted[p];
    const unsigned q = __float_as_uint(sp.w);
    const float  qx  = sp.x, qy = sp.y, sqi = sp.z;
    const float  m2x = -2.0f * qx, m2y = -2.0f * qy;  // exact (×2)
    const int bx = bin_of(qx);
    const int by = bin_of(qy);

    // exact reference-rounded key: (fkey(d2) << 32) | idx
    auto exact_key = [&](float px, float py, float pz, unsigned j) -> unsigned long long {
        float dot = __fmaf_rn(py, qy, __fmul_rn(px, qx));
        float d2  = __fsub_rn(__fadd_rn(sqi, pz), __fmul_rn(2.0f, dot));
        if (j == q) d2 = INF;  // no self loops
        return ((unsigned long long)fkey(d2) << 32) | j;
    };

    unsigned long long slot = PADKEY;  // slots start +inf, stay sorted asc
    float curMax = INF;
    float thresh = INF;

    auto update_thresh = [&]() {
        unsigned hi = (unsigned)(__shfl_sync(FULL, slot, 31) >> 32);
        // PAD sentinel decodes to NaN -> clamp to +INF
        curMax = (hi == PADHI) ? INF : unfkey(hi);
        thresh = (hi == PADHI) ? INF : (curMax - sqi + 2e-5f);
    };

    auto scan_range = [&](int lo, int hiend) {
        for (int base = lo; base < hiend; base += 32) {
            int i = base + lane;
            float4 pp = make_float4(0.0f, 0.0f, INF, 0.0f);
            float score = INF;
            unsigned jidx = 0;
            if (i < hiend) {
                pp = g_sorted[i];
                jidx = __float_as_uint(pp.w);
                score = __fmaf_rn(pp.y, m2y, __fmaf_rn(pp.x, m2x, pp.z));
            }
            bool hit = (score < thresh);   // score=INF when i>=hiend
            unsigned mask = __ballot_sync(FULL, hit);
            if (!mask) continue;
            unsigned long long ck = hit ? exact_key(pp.x, pp.y, pp.z, jidx)
                                        : PADKEY;
            if (__popc(mask) <= 12) {
                // few hits: serial shift-insert (self-rejecting);
                // breakeven vs 20-stage merge is ~12 hits
                do {
                    int srcl = __ffs(mask) - 1;
                    mask &= mask - 1;
                    unsigned long long kk = __shfl_sync(FULL, ck, srcl);
                    bool gt = (slot > kk);
                    unsigned mm = __ballot_sync(FULL, gt);
                    unsigned long long o = __shfl_up_sync(FULL, slot, 1);
                    if (gt) slot = (lane == __ffs(mm) - 1) ? kk : o;
                } while (mask);
            } else {
                // many hits: bitonic sort candidates asc (15 stages)
                #pragma unroll
                for (int k2 = 2; k2 <= 32; k2 <<= 1) {
                    #pragma unroll
                    for (int j = k2 >> 1; j > 0; j >>= 1) {
                        unsigned long long o = __shfl_xor_sync(FULL, ck, j);
                        bool keepmin = (((lane & k2) == 0) == ((lane & j) == 0));
                        ck = keepmin ? umin64(ck, o) : umax64(ck, o);
                    }
                }
                // top-32 merge: min(A, reverse(B)) bitonic; 5-stage clean
                unsigned long long br = __shfl_sync(FULL, ck, 31 - lane);
                unsigned long long m  = umin64(slot, br);
                #pragma unroll
                for (int j = 16; j > 0; j >>= 1) {
                    unsigned long long o = __shfl_xor_sync(FULL, m, j);
                    m = ((lane & j) == 0) ? umin64(m, o) : umax64(m, o);
                }
                slot = m;
            }
            update_thresh();
        }
    };

    // home bin FIRST (tightest early threshold), then rest of 3-bin row
    const int bxlo1 = max(bx - 1, 0), bxhi1 = min(bx + 1, G - 1);
    const int rowb = by * G;
    const int hsb = g_binStart[rowb + bx], heb = g_binStart[rowb + bx + 1];
    scan_range(hsb, heb);
    scan_range(g_binStart[rowb + bxlo1], hsb);
    scan_range(heb, g_binStart[rowb + bxhi1 + 1]);
    if (by - 1 >= 0) {
        int r = (by - 1) * G;
        scan_range(g_binStart[r + bxlo1], g_binStart[r + bxhi1 + 1]);
    }
    if (by + 1 <= G - 1) {
        int r = (by + 1) * G;
        scan_range(g_binStart[r + bxlo1], g_binStart[r + bxhi1 + 1]);
    }

    // Chebyshev rings m>=2 with exact stop bound (curMax=INF never stops)
    for (int m = 2; m <= 2 * G; m++) {
        {
            int mm1 = m - 1;
            float dl = (bx - mm1 > 0)     ? (qx - (X0 + (bx - mm1) * SW))     : INF;
            float dr = (bx + mm1 < G - 1) ? ((X0 + (bx + mm1 + 1) * SW) - qx) : INF;
            float db = (by - mm1 > 0)     ? (qy - (X0 + (by - mm1) * SW))     : INF;
            float dt = (by + mm1 < G - 1) ? ((X0 + (by + mm1 + 1) * SW) - qy) : INF;
            float dmin = fminf(fminf(dl, dr), fminf(db, dt));
            if (dmin * dmin > curMax + 2e-5f) break;
        }
        int bxlo = max(bx - m, 0), bxhi = min(bx + m, G - 1);
        if (by - m >= 0) {
            int r = (by - m) * G;
            scan_range(g_binStart[r + bxlo], g_binStart[r + bxhi + 1]);
        }
        if (by + m <= G - 1) {
            int r = (by + m) * G;
            scan_range(g_binStart[r + bxlo], g_binStart[r + bxhi + 1]);
        }
        int ylo = max(by - m + 1, 0), yhi = min(by + m - 1, G - 1);
        if (bx - m >= 0) {
            for (int y = ylo; y <= yhi; y++) {
                int bb = y * G + bx - m;
                scan_range(g_binStart[bb], g_binStart[bb + 1]);
            }
        }
        if (bx + m <= G - 1) {
            for (int y = ylo; y <= yhi; y++) {
                int bb = y * G + bx + m;
                scan_range(g_binStart[bb], g_binStart[bb + 1]);
            }
        }
    }

    // ---- outputs (slots ascending = exact top_k order) ----
    const int e = (int)q * KNN + lane;
    const int s = (int)(unsigned)(slot & 0xffffffffu);

    out[e]      = (float)s;        // edge_index[0] (sources)
    out[NE + e] = (float)q;        // edge_index[1] (targets)

    float4 as = g_attr[s];
    float4 at = g_attr[q];
    float hsum = __fadd_rn(as.y, at.y);
    float f1 = __fdiv_rn(__fmul_rn(2.0f, __fsub_rn(as.z, at.z)), hsum);
    float f2 = __fdiv_rn(__fmul_rn(2.0f, __fsub_rn(as.w, at.w)), hsum);
    float f3 = logf(__fdiv_rn(as.x, at.x));
    float f4 = logf(__fdiv_rn(as.y, at.y));

    float4* ao = reinterpret_cast<float4*>(out + 2 * NE) + e;
    *ao = make_float4(f1, f2, f3, f4);
}

extern "C" void kernel_launch(void* const* d_in, const int* in_sizes, int n_in,
                              void* d_out, int out_size) {
    const float* loc = (const float*)d_in[1];
    float* out = (float*)d_out;

    fused_kernel<<<NBLK, TPB>>>(loc, out);
}

// round 13
// speedup vs baseline: 1.1846x; 1.0433x over previous
#include <cuda_runtime.h>
#include <cstdint>

#define N_NODES 8192
#define KNN     32
#define NE      (N_NODES * KNN)
#define FULL    0xffffffffu

#define G       16
#define NBINS   (G * G)
#define X0      0.1f
#define SINV    (G / 0.9f)     // bins per coordinate unit
#define SW      (0.9f / G)     // bin width

#define NBLK    1024
#define TPB     256
#define WPB     (TPB / 32)             // 8 warps/block
#define PREPB   32                     // prep blocks; 1 point per thread

#define PADKEY  0xffffffffffffffffULL
#define PADHI   0xffffffffu

// Scratch (__device__ globals; zero-initialized at load; all mutable state is
// reset at the very END of each run, off the critical path, for graph replay)
__device__ float4 g_attr[N_NODES];     // {w, h, cx, cy} original order
__device__ float4 g_sorted[N_NODES];   // bin order: {cx, cy, sq, bits(idx)}
__device__ int    g_binStart[NBINS + 1];
__device__ int    g_hist[NBINS];
__device__ int    g_bar1, g_flagB, g_scat, g_ready, g_fin;

__device__ __forceinline__ int bin_of(float c) {
    int b = (int)((c - X0) * SINV);
    return min(max(b, 0), G - 1);
}

// monotonic float<->uint order mapping
__device__ __forceinline__ unsigned fkey(float f) {
    unsigned u = __float_as_uint(f);
    return (u & 0x80000000u) ? ~u : (u | 0x80000000u);
}
__device__ __forceinline__ float unfkey(unsigned k) {
    unsigned u = (k & 0x80000000u) ? (k ^ 0x80000000u) : ~k;
    return __uint_as_float(u);
}

__device__ __forceinline__ unsigned long long umin64(unsigned long long a,
                                                     unsigned long long b) {
    return a < b ? a : b;
}
__device__ __forceinline__ unsigned long long umax64(unsigned long long a,
                                                     unsigned long long b) {
    return a > b ? a : b;
}

__global__ void __launch_bounds__(TPB, 8)   // 8 blocks/SM, 64 warps/SM, regs<=32
fused_kernel(const float* __restrict__ loc, float* __restrict__ out) {
    const int t = threadIdx.x;
    const int b = blockIdx.x;
    const int lane = t & 31;
    const float INF = __int_as_float(0x7f800000);

    // ============ Prep (blocks 0..PREPB-1 only; 1 point per thread) ======
    if (b < PREPB) {
        const int ir = b * TPB + t;
        // row byte offset 40*i+16 is 8-aligned -> float2 loads [w,h],[cx,cy]
        const float2* p2 = reinterpret_cast<const float2*>(loc + ir * 10 + 4);
        float2 wh = p2[0];
        float2 cc = p2[1];
        // sq matches jnp.sum(pos*pos): rn(cx*cx)+rn(cy*cy), no fma
        float sq = __fadd_rn(__fmul_rn(cc.x, cc.x), __fmul_rn(cc.y, cc.y));
        g_attr[ir] = make_float4(wh.x, wh.y, cc.x, cc.y);
        int bin = bin_of(cc.y) * G + bin_of(cc.x);
        int rank = atomicAdd(&g_hist[bin], 1);   // global in-bin rank
        __threadfence();
        __syncthreads();
        if (t == 0) atomicAdd(&g_bar1, 1);

        // block 0 scans the 256 bins once all hist contributions landed
        if (b == 0) {
            if (t == 0) {
                while (((volatile int*)&g_bar1)[0] < PREPB) __nanosleep(32);
            }
            __syncthreads();
            __threadfence();
            __shared__ int wsum[8];
            int v = 0, h = 0;
            if (t < NBINS) {
                h = g_hist[t];
                v = h;
                #pragma unroll
                for (int off = 1; off < 32; off <<= 1) {
                    int n = __shfl_up_sync(FULL, v, off);
                    if (lane >= off) v += n;
                }
                if (lane == 31) wsum[t >> 5] = v;
            }
            __syncthreads();
            if (t < 8) {
                int s = wsum[t];
                #pragma unroll
                for (int off = 1; off < 8; off <<= 1) {
                    int n = __shfl_up_sync(0xffu, s, off);
                    if (t >= off) s += n;
                }
                wsum[t] = s;
            }
            __syncthreads();
            if (t < NBINS) {
                int incl = v + ((t >= 32) ? wsum[(t >> 5) - 1] : 0);
                g_binStart[t] = incl - h;
                if (t == NBINS - 1) g_binStart[NBINS] = incl;
            }
            __threadfence();
            __syncthreads();
            if (t == 0) atomicExch(&g_flagB, 1);
        }
        if (t == 0) {
            while (((volatile int*)&g_flagB)[0] == 0) __nanosleep(32);
        }
        __syncthreads();
        __threadfence();

        // scatter at binStart + rank
        g_sorted[g_binStart[bin] + rank] =
            make_float4(cc.x, cc.y, sq, __uint_as_float((unsigned)ir));
        __threadfence();
        __syncthreads();
        if (t == 0) {
            int o = atomicAdd(&g_scat, 1);
            if (o == PREPB - 1) {          // last prep block: publish ready
                __threadfence();
                atomicExch(&g_ready, 1);
            }
        }
    }

    // ============ ALL blocks: single read-only poll until data ready =====
    if (t == 0) {
        while (((volatile int*)&g_ready)[0] == 0) __nanosleep(64);
    }
    __syncthreads();
    __threadfence();

    // ================= Phase D: KNN (1 query per warp) ====================
    const int p = b * WPB + (t >> 5);   // sorted position (bin-ordered)

    const float4 sp = g_sorted[p];
    const unsigned q = __float_as_uint(sp.w);
    const float  qx  = sp.x, qy = sp.y, sqi = sp.z;
    const float  m2x = -2.0f * qx, m2y = -2.0f * qy;  // exact (×2)
    const int bx = bin_of(qx);
    const int by = bin_of(qy);

    // exact reference-rounded key: (fkey(d2) << 32) | idx
    auto exact_key = [&](float px, float py, float pz, unsigned j) -> unsigned long long {
        float dot = __fmaf_rn(py, qy, __fmul_rn(px, qx));
        float d2  = __fsub_rn(__fadd_rn(sqi, pz), __fmul_rn(2.0f, dot));
        if (j == q) d2 = INF;  // no self loops
        return ((unsigned long long)fkey(d2) << 32) | j;
    };

    unsigned long long slot = PADKEY;  // slots start +inf, stay sorted asc
    float curMax = INF;
    float thresh = INF;

    auto update_thresh = [&]() {
        unsigned hi = (unsigned)(__shfl_sync(FULL, slot, 31) >> 32);
        // PAD sentinel decodes to NaN -> clamp to +INF
        curMax = (hi == PADHI) ? INF : unfkey(hi);
        thresh = (hi == PADHI) ? INF : (curMax - sqi + 2e-5f);
    };

    auto scan_range = [&](int lo, int hiend) {
        for (int base = lo; base < hiend; base += 32) {
            int i = base + lane;
            float4 pp = make_float4(0.0f, 0.0f, INF, 0.0f);
            float score = INF;
            unsigned jidx = 0;
            if (i < hiend) {
                pp = g_sorted[i];
                jidx = __float_as_uint(pp.w);
                score = __fmaf_rn(pp.y, m2y, __fmaf_rn(pp.x, m2x, pp.z));
            }
            bool hit = (score < thresh);   // score=INF when i>=hiend
            unsigned mask = __ballot_sync(FULL, hit);
            if (!mask) continue;
            unsigned long long ck = hit ? exact_key(pp.x, pp.y, pp.z, jidx)
                                        : PADKEY;
            if (__popc(mask) <= 12) {
                // few hits: serial shift-insert (self-rejecting);
                // breakeven vs 20-stage merge is ~12 hits
                do {
                    int srcl = __ffs(mask) - 1;
                    mask &= mask - 1;
                    unsigned long long kk = __shfl_sync(FULL, ck, srcl);
                    bool gt = (slot > kk);
                    unsigned mm = __ballot_sync(FULL, gt);
                    unsigned long long o = __shfl_up_sync(FULL, slot, 1);
                    if (gt) slot = (lane == __ffs(mm) - 1) ? kk : o;
                } while (mask);
            } else {
                // many hits: bitonic sort candidates asc (15 stages)
                #pragma unroll
                for (int k2 = 2; k2 <= 32; k2 <<= 1) {
                    #pragma unroll
                    for (int j = k2 >> 1; j > 0; j >>= 1) {
                        unsigned long long o = __shfl_xor_sync(FULL, ck, j);
                        bool keepmin = (((lane & k2) == 0) == ((lane & j) == 0));
                        ck = keepmin ? umin64(ck, o) : umax64(ck, o);
                    }
                }
                // top-32 merge: min(A, reverse(B)) bitonic; 5-stage clean
                unsigned long long br = __shfl_sync(FULL, ck, 31 - lane);
                unsigned long long m  = umin64(slot, br);
                #pragma unroll
                for (int j = 16; j > 0; j >>= 1) {
                    unsigned long long o = __shfl_xor_sync(FULL, m, j);
                    m = ((lane & j) == 0) ? umin64(m, o) : umax64(m, o);
                }
                slot = m;
            }
            update_thresh();
        }
    };

    // home bin FIRST (tightest early threshold), then rest of 3-bin row
    const int bxlo1 = max(bx - 1, 0), bxhi1 = min(bx + 1, G - 1);
    const int rowb = by * G;
    const int hsb = g_binStart[rowb + bx], heb = g_binStart[rowb + bx + 1];
    scan_range(hsb, heb);
    scan_range(g_binStart[rowb + bxlo1], hsb);
    scan_range(heb, g_binStart[rowb + bxhi1 + 1]);
    if (by - 1 >= 0) {
        int r = (by - 1) * G;
        scan_range(g_binStart[r + bxlo1], g_binStart[r + bxhi1 + 1]);
    }
    if (by + 1 <= G - 1) {
        int r = (by + 1) * G;
        scan_range(g_binStart[r + bxlo1], g_binStart[r + bxhi1 + 1]);
    }

    // Chebyshev rings m>=2 with exact stop bound (curMax=INF never stops)
    for (int m = 2; m <= 2 * G; m++) {
        {
            int mm1 = m - 1;
            float dl = (bx - mm1 > 0)     ? (qx - (X0 + (bx - mm1) * SW))     : INF;
            float dr = (bx + mm1 < G - 1) ? ((X0 + (bx + mm1 + 1) * SW) - qx) : INF;
            float db = (by - mm1 > 0)     ? (qy - (X0 + (by - mm1) * SW))     : INF;
            float dt = (by + mm1 < G - 1) ? ((X0 + (by + mm1 + 1) * SW) - qy) : INF;
            float dmin = fminf(fminf(dl, dr), fminf(db, dt));
            if (dmin * dmin > curMax + 2e-5f) break;
        }
        int bxlo = max(bx - m, 0), bxhi = min(bx + m, G - 1);
        if (by - m >= 0) {
            int r = (by - m) * G;
            scan_range(g_binStart[r + bxlo], g_binStart[r + bxhi + 1]);
        }
        if (by + m <= G - 1) {
            int r = (by + m) * G;
            scan_range(g_binStart[r + bxlo], g_binStart[r + bxhi + 1]);
        }
        int ylo = max(by - m + 1, 0), yhi = min(by + m - 1, G - 1);
        if (bx - m >= 0) {
            for (int y = ylo; y <= yhi; y++) {
                int bb = y * G + bx - m;
                scan_range(g_binStart[bb], g_binStart[bb + 1]);
            }
        }
        if (bx + m <= G - 1) {
            for (int y = ylo; y <= yhi; y++) {
                int bb = y * G + bx + m;
                scan_range(g_binStart[bb], g_binStart[bb + 1]);
            }
        }
    }

    // ---- outputs (slots ascending = exact top_k order) ----
    const int e = (int)q * KNN + lane;
    const int s = (int)(unsigned)(slot & 0xffffffffu);

    out[e]      = (float)s;        // edge_index[0] (sources)
    out[NE + e] = (float)q;        // edge_index[1] (targets)

    float4 as = g_attr[s];
    float4 at = g_attr[q];
    float hsum = __fadd_rn(as.y, at.y);
    float f1 = __fdiv_rn(__fmul_rn(2.0f, __fsub_rn(as.z, at.z)), hsum);
    float f2 = __fdiv_rn(__fmul_rn(2.0f, __fsub_rn(as.w, at.w)), hsum);
    float f3 = logf(__fdiv_rn(as.x, at.x));
    float f4 = logf(__fdiv_rn(as.y, at.y));

    float4* ao = reinterpret_cast<float4*>(out + 2 * NE) + e;
    *ao = make_float4(f1, f2, f3, f4);

    // ============ End-of-run state reset (OFF the critical path) =========
    __threadfence();
    __syncthreads();
    if (t == 0) {
        int o = atomicAdd(&g_fin, 1);
        if (o == NBLK - 1) {   // last block out: restore load-time state
            #pragma unroll 4
            for (int i = 0; i < NBINS; i++) g_hist[i] = 0;
            g_bar1 = 0; g_flagB = 0; g_scat = 0; g_ready = 0; g_fin = 0;
            __threadfence();
        }
    }
}

extern "C" void kernel_launch(void* const* d_in, const int* in_sizes, int n_in,
                              void* d_out, int out_size) {
    const float* loc = (const float*)d_in[1];
    float* out = (float*)d_out;

    fused_kernel<<<NBLK, TPB>>>(loc, out);
}